// round 3
// baseline (speedup 1.0000x reference)
#include <cuda_runtime.h>
#include <cuda_bf16.h>
#include <stdint.h>

// GAE forward: A_hat = sigmoid(Z Z^T), Z = A @ (relu(A @ (X W1)) @ W2)
// N=8192, F_IN=256, HID=128, LAT=32. All heavy GEMMs in bf16 mma.sync with
// fp32 accumulation; numerically safe (output = 0.5 + O(1e-8), tol 1e-3).

constexpr int NN  = 8192;
constexpr int FIN = 256;
constexpr int HID = 128;
constexpr int LAT = 32;

// Scratch (no cudaMalloc allowed): 5 MB total.
__device__ __nv_bfloat16 g_C1t[HID * NN];  // (X W1)^T   [128][8192] bf16
__device__ __nv_bfloat16 g_H  [NN * HID];  // relu(A@C1) [8192][128] bf16
__device__ __nv_bfloat16 g_C2t[LAT * NN];  // (H W2)^T   [32][8192]  bf16
__device__ __nv_bfloat16 g_Z  [NN * LAT];  // Z          [8192][32]  bf16

__device__ __forceinline__ void mma_bf16(float c[4], const uint32_t a[4], const uint32_t b[2]) {
    asm volatile(
        "mma.sync.aligned.m16n8k16.row.col.f32.bf16.bf16.f32 "
        "{%0,%1,%2,%3}, {%4,%5,%6,%7}, {%8,%9}, {%0,%1,%2,%3};\n"
        : "+f"(c[0]), "+f"(c[1]), "+f"(c[2]), "+f"(c[3])
        : "r"(a[0]), "r"(a[1]), "r"(a[2]), "r"(a[3]), "r"(b[0]), "r"(b[1]));
}

__device__ __forceinline__ uint32_t pack_bf16x2(float x, float y) {
    __nv_bfloat162 v = __float22bfloat162_rn(make_float2(x, y));
    return *reinterpret_cast<uint32_t*>(&v);
}

__device__ __forceinline__ float sigmoid_f(float x) {
    float ax = fabsf(x);
    if (ax < 1.0f) {
        // odd Taylor: 1/2 + x/4 - x^3/48 + x^5/480 ; |err| < 2.2e-5 on |x|<1
        float x2 = x * x;
        return 0.5f + x * (0.25f + x2 * (-(1.0f / 48.0f) + x2 * (1.0f / 480.0f)));
    }
    return 1.0f / (1.0f + __expf(-x));
}

// ---------------------------------------------------------------------------
// k0: C1t = (X @ W1)^T as bf16.  SIMT fp32, 0.54 GFLOP.
// grid 128, block 256. BM=64, BN=128(all), BK=32.
// ---------------------------------------------------------------------------
__global__ __launch_bounds__(256) void k0_xw1(const float* __restrict__ X,
                                              const float* __restrict__ W1) {
    __shared__ float Xs[64][32];
    __shared__ float Ws[32][128];
    const int tid = threadIdx.x;
    const int r0  = blockIdx.x * 64;
    const int ty  = tid >> 5, tx = tid & 31;

    float acc[8][4];
#pragma unroll
    for (int i = 0; i < 8; ++i)
#pragma unroll
        for (int j = 0; j < 4; ++j) acc[i][j] = 0.0f;

    for (int kt = 0; kt < FIN; kt += 32) {
#pragma unroll
        for (int j = 0; j < 2; ++j) {
            int id = tid + j * 256;
            int rr = id >> 3, cc = (id & 7) * 4;
            *(float4*)&Xs[rr][cc] = *(const float4*)&X[(size_t)(r0 + rr) * FIN + kt + cc];
        }
#pragma unroll
        for (int j = 0; j < 4; ++j) {
            int id = tid + j * 256;
            int rr = id >> 5, cc = (id & 31) * 4;
            *(float4*)&Ws[rr][cc] = *(const float4*)&W1[(size_t)(kt + rr) * HID + cc];
        }
        __syncthreads();
#pragma unroll
        for (int k = 0; k < 32; ++k) {
            float4 b = *(float4*)&Ws[k][tx * 4];
#pragma unroll
            for (int i = 0; i < 8; ++i) {
                float a = Xs[ty * 8 + i][k];
                acc[i][0] += a * b.x;
                acc[i][1] += a * b.y;
                acc[i][2] += a * b.z;
                acc[i][3] += a * b.w;
            }
        }
        __syncthreads();
    }
#pragma unroll
    for (int i = 0; i < 8; ++i)
#pragma unroll
        for (int j = 0; j < 4; ++j)
            g_C1t[(size_t)(tx * 4 + j) * NN + r0 + ty * 8 + i] = __float2bfloat16(acc[i][j]);
}

// ---------------------------------------------------------------------------
// k1: H = relu(A @ C1), bf16 mma.sync. BM=64, BN=128, BK=32. grid 128.
// 8 warps: 4(M) x 2(N); warp tile 16x64 (8 n-frags). 256 K-chunks.
// ---------------------------------------------------------------------------
__global__ __launch_bounds__(256) void k1_gemm1(const float* __restrict__ A) {
    __shared__ __nv_bfloat16 As[64][40];   // [m][k], pad->conflict-free frag reads
    __shared__ __nv_bfloat16 Bs[128][40];  // [n][k] (C1t rows copy straight in)

    const int tid  = threadIdx.x;
    const int warp = tid >> 5, lane = tid & 31;
    const int g = lane >> 2, t = lane & 3;
    const int m0 = (warp & 3) * 16, n0 = (warp >> 2) * 64;
    const int r0 = blockIdx.x * 64;

    float acc[8][4];
#pragma unroll
    for (int f = 0; f < 8; ++f)
#pragma unroll
        for (int j = 0; j < 4; ++j) acc[f][j] = 0.0f;

    float4 pa[2];
    uint4  pb[2];
    // prefetch chunk 0
#pragma unroll
    for (int j = 0; j < 2; ++j) {
        int id = tid + j * 256;
        int ar = id >> 3, ac = (id & 7) * 4;
        pa[j] = *(const float4*)&A[(size_t)(r0 + ar) * NN + ac];
        int bn = id >> 2, bk = (id & 3) * 8;
        pb[j] = *(const uint4*)&g_C1t[(size_t)bn * NN + bk];
    }

    const int NKT = NN / 32;
    for (int kt = 0; kt < NKT; ++kt) {
        // regs -> smem
#pragma unroll
        for (int j = 0; j < 2; ++j) {
            int id = tid + j * 256;
            int ar = id >> 3, ac = (id & 7) * 4;
            uint2 pk = make_uint2(pack_bf16x2(pa[j].x, pa[j].y),
                                  pack_bf16x2(pa[j].z, pa[j].w));
            *(uint2*)&As[ar][ac] = pk;
            int bn = id >> 2, bk = (id & 3) * 8;
            *(uint4*)&Bs[bn][bk] = pb[j];
        }
        __syncthreads();
        if (kt + 1 < NKT) {
            int koff = (kt + 1) * 32;
#pragma unroll
            for (int j = 0; j < 2; ++j) {
                int id = tid + j * 256;
                int ar = id >> 3, ac = (id & 7) * 4;
                pa[j] = *(const float4*)&A[(size_t)(r0 + ar) * NN + koff + ac];
                int bn = id >> 2, bk = (id & 3) * 8;
                pb[j] = *(const uint4*)&g_C1t[(size_t)bn * NN + koff + bk];
            }
        }
#pragma unroll
        for (int ks = 0; ks < 32; ks += 16) {
            uint32_t a[4];
            a[0] = *(uint32_t*)&As[m0 + g    ][ks + 2 * t    ];
            a[1] = *(uint32_t*)&As[m0 + g + 8][ks + 2 * t    ];
            a[2] = *(uint32_t*)&As[m0 + g    ][ks + 2 * t + 8];
            a[3] = *(uint32_t*)&As[m0 + g + 8][ks + 2 * t + 8];
#pragma unroll
            for (int f = 0; f < 8; ++f) {
                uint32_t b[2];
                b[0] = *(uint32_t*)&Bs[n0 + f * 8 + g][ks + 2 * t    ];
                b[1] = *(uint32_t*)&Bs[n0 + f * 8 + g][ks + 2 * t + 8];
                mma_bf16(acc[f], a, b);
            }
        }
        __syncthreads();
    }
    // epilogue: relu -> bf16 H row-major
#pragma unroll
    for (int f = 0; f < 8; ++f) {
        int col = n0 + f * 8 + 2 * t;
        int row = r0 + m0 + g;
        uint32_t v0 = pack_bf16x2(fmaxf(acc[f][0], 0.0f), fmaxf(acc[f][1], 0.0f));
        uint32_t v1 = pack_bf16x2(fmaxf(acc[f][2], 0.0f), fmaxf(acc[f][3], 0.0f));
        *(uint32_t*)&g_H[(size_t)row * HID + col]       = v0;
        *(uint32_t*)&g_H[(size_t)(row + 8) * HID + col] = v1;
    }
}

// ---------------------------------------------------------------------------
// k2: C2t = (H @ W2)^T bf16. SIMT, tiny (67 MFLOP). grid 128, block 256.
// ---------------------------------------------------------------------------
__global__ __launch_bounds__(256) void k2_hw2(const float* __restrict__ W2) {
    __shared__ float          Ws[HID * LAT];   // 16 KB
    __shared__ __nv_bfloat16  Hs[64 * HID];    // 16 KB
    const int tid = threadIdx.x;
    const int r0  = blockIdx.x * 64;
#pragma unroll
    for (int j = 0; j < 16; ++j) Ws[tid + j * 256] = W2[tid + j * 256];
#pragma unroll
    for (int j = 0; j < 4; ++j)
        ((uint4*)Hs)[tid + j * 256] =
            ((const uint4*)(g_H + (size_t)r0 * HID))[tid + j * 256];
    __syncthreads();

    const int c = tid & 31, rb = tid >> 5;
    float acc[8];
#pragma unroll
    for (int i = 0; i < 8; ++i) acc[i] = 0.0f;
    for (int k = 0; k < HID; ++k) {
        float w = Ws[k * LAT + c];
#pragma unroll
        for (int i = 0; i < 8; ++i)
            acc[i] += __bfloat162float(Hs[(rb + i * 8) * HID + k]) * w;
    }
#pragma unroll
    for (int i = 0; i < 8; ++i)
        g_C2t[(size_t)c * NN + r0 + rb + i * 8] = __float2bfloat16(acc[i]);
}

// ---------------------------------------------------------------------------
// k3: Z = A @ C2, bf16 mma. BM=64, BN=32, BK=64. grid 128.
// 8 warps: 4(M) x 2(N); warp tile 16x16 (2 n-frags). 128 K-chunks.
// ---------------------------------------------------------------------------
__global__ __launch_bounds__(256) void k3_gemm2(const float* __restrict__ A) {
    __shared__ __nv_bfloat16 As[64][72];
    __shared__ __nv_bfloat16 Bs[32][72];

    const int tid  = threadIdx.x;
    const int warp = tid >> 5, lane = tid & 31;
    const int g = lane >> 2, t = lane & 3;
    const int m0 = (warp & 3) * 16, n0 = (warp >> 2) * 16;
    const int r0 = blockIdx.x * 64;

    float acc[2][4];
#pragma unroll
    for (int f = 0; f < 2; ++f)
#pragma unroll
        for (int j = 0; j < 4; ++j) acc[f][j] = 0.0f;

    float4 pa[4];
    uint4  pb;
    const int bnB = tid >> 3, bkB = (tid & 7) * 8;
#pragma unroll
    for (int j = 0; j < 4; ++j) {
        int id = tid + j * 256;
        int ar = id >> 4, ac = (id & 15) * 4;
        pa[j] = *(const float4*)&A[(size_t)(r0 + ar) * NN + ac];
    }
    pb = *(const uint4*)&g_C2t[(size_t)bnB * NN + bkB];

    const int NKT = NN / 64;
    for (int kt = 0; kt < NKT; ++kt) {
#pragma unroll
        for (int j = 0; j < 4; ++j) {
            int id = tid + j * 256;
            int ar = id >> 4, ac = (id & 15) * 4;
            uint2 pk = make_uint2(pack_bf16x2(pa[j].x, pa[j].y),
                                  pack_bf16x2(pa[j].z, pa[j].w));
            *(uint2*)&As[ar][ac] = pk;
        }
        *(uint4*)&Bs[bnB][bkB] = pb;
        __syncthreads();
        if (kt + 1 < NKT) {
            int koff = (kt + 1) * 64;
#pragma unroll
            for (int j = 0; j < 4; ++j) {
                int id = tid + j * 256;
                int ar = id >> 4, ac = (id & 15) * 4;
                pa[j] = *(const float4*)&A[(size_t)(r0 + ar) * NN + koff + ac];
            }
            pb = *(const uint4*)&g_C2t[(size_t)bnB * NN + koff + bkB];
        }
#pragma unroll
        for (int ks = 0; ks < 64; ks += 16) {
            uint32_t a[4];
            a[0] = *(uint32_t*)&As[m0 + g    ][ks + 2 * t    ];
            a[1] = *(uint32_t*)&As[m0 + g + 8][ks + 2 * t    ];
            a[2] = *(uint32_t*)&As[m0 + g    ][ks + 2 * t + 8];
            a[3] = *(uint32_t*)&As[m0 + g + 8][ks + 2 * t + 8];
#pragma unroll
            for (int f = 0; f < 2; ++f) {
                uint32_t b[2];
                b[0] = *(uint32_t*)&Bs[n0 + f * 8 + g][ks + 2 * t    ];
                b[1] = *(uint32_t*)&Bs[n0 + f * 8 + g][ks + 2 * t + 8];
                mma_bf16(acc[f], a, b);
            }
        }
        __syncthreads();
    }
#pragma unroll
    for (int f = 0; f < 2; ++f) {
        int col = n0 + f * 8 + 2 * t;
        int row = r0 + m0 + g;
        *(uint32_t*)&g_Z[(size_t)row * LAT + col]       = pack_bf16x2(acc[f][0], acc[f][1]);
        *(uint32_t*)&g_Z[(size_t)(row + 8) * LAT + col] = pack_bf16x2(acc[f][2], acc[f][3]);
    }
}

// ---------------------------------------------------------------------------
// k4: out = sigmoid(Z @ Z^T). 128x128 tile/block, grid 64x64, K=32.
// Both mma operands are Z rows (B fragment *is* Z^T). Poly sigmoid.
// ---------------------------------------------------------------------------
__global__ __launch_bounds__(256) void k4_decoder(float* __restrict__ out) {
    __shared__ __nv_bfloat16 Zi[128][40];
    __shared__ __nv_bfloat16 Zj[128][40];
    const int tid  = threadIdx.x;
    const int warp = tid >> 5, lane = tid & 31;
    const int g = lane >> 2, t = lane & 3;
    const int m0 = (warp & 3) * 32, n0 = (warp >> 2) * 64;
    const size_t i0 = (size_t)blockIdx.y * 128;
    const size_t j0 = (size_t)blockIdx.x * 128;

#pragma unroll
    for (int j = 0; j < 2; ++j) {
        int id = tid + j * 256;
        int rr = id >> 2, kk = (id & 3) * 8;
        *(uint4*)&Zi[rr][kk] = *(const uint4*)&g_Z[(i0 + rr) * LAT + kk];
        *(uint4*)&Zj[rr][kk] = *(const uint4*)&g_Z[(j0 + rr) * LAT + kk];
    }
    __syncthreads();

    float acc[2][8][4];
#pragma unroll
    for (int mt = 0; mt < 2; ++mt)
#pragma unroll
        for (int f = 0; f < 8; ++f)
#pragma unroll
            for (int j = 0; j < 4; ++j) acc[mt][f][j] = 0.0f;

#pragma unroll
    for (int ks = 0; ks < 32; ks += 16) {
        uint32_t a[2][4];
#pragma unroll
        for (int mt = 0; mt < 2; ++mt) {
            int mr = m0 + mt * 16;
            a[mt][0] = *(uint32_t*)&Zi[mr + g    ][ks + 2 * t    ];
            a[mt][1] = *(uint32_t*)&Zi[mr + g + 8][ks + 2 * t    ];
            a[mt][2] = *(uint32_t*)&Zi[mr + g    ][ks + 2 * t + 8];
            a[mt][3] = *(uint32_t*)&Zi[mr + g + 8][ks + 2 * t + 8];
        }
#pragma unroll
        for (int f = 0; f < 8; ++f) {
            uint32_t b[2];
            b[0] = *(uint32_t*)&Zj[n0 + f * 8 + g][ks + 2 * t    ];
            b[1] = *(uint32_t*)&Zj[n0 + f * 8 + g][ks + 2 * t + 8];
#pragma unroll
            for (int mt = 0; mt < 2; ++mt) mma_bf16(acc[mt][f], a[mt], b);
        }
    }

#pragma unroll
    for (int mt = 0; mt < 2; ++mt) {
#pragma unroll
        for (int f = 0; f < 8; ++f) {
            size_t row = i0 + m0 + mt * 16 + g;
            size_t col = j0 + n0 + f * 8 + 2 * t;
            float2 v0 = make_float2(sigmoid_f(acc[mt][f][0]), sigmoid_f(acc[mt][f][1]));
            float2 v1 = make_float2(sigmoid_f(acc[mt][f][2]), sigmoid_f(acc[mt][f][3]));
            *(float2*)&out[row * NN + col]       = v0;
            *(float2*)&out[(row + 8) * NN + col] = v1;
        }
    }
}

// ---------------------------------------------------------------------------
extern "C" void kernel_launch(void* const* d_in, const int* in_sizes, int n_in,
                              void* d_out, int out_size) {
    const float* X  = (const float*)d_in[0];
    const float* A  = (const float*)d_in[1];
    const float* W1 = (const float*)d_in[2];
    const float* W2 = (const float*)d_in[3];
    float* out = (float*)d_out;
    (void)in_sizes; (void)n_in; (void)out_size;

    k0_xw1  <<<NN / 64, 256>>>(X, W1);
    k1_gemm1<<<NN / 64, 256>>>(A);
    k2_hw2  <<<NN / 64, 256>>>(W2);
    k3_gemm2<<<NN / 64, 256>>>(A);
    dim3 grid(NN / 128, NN / 128);
    k4_decoder<<<grid, 256>>>(out);
}